// round 16
// baseline (speedup 1.0000x reference)
#include <cuda_runtime.h>
#include <cuda_bf16.h>
#include <cstdint>

constexpr int B = 32;
constexpr int A = 16384;
constexpr int C = 81;

constexpr int APB  = 32;            // anchors per ce block
constexpr int FPB  = APB * C;       // 2592 floats
constexpr int V4PB = FPB / 4;       // 648 float4
constexpr int WPB  = A / 32;        // 512 mask words per batch

// Scratch (device globals; no allocations allowed).
__device__ float    g_maxce[B * A];         // slow path only
__device__ unsigned g_posmask[B * WPB];     // bit: depth > 0
__device__ unsigned g_zeromask[B * WPB];    // bit: v == 0  (v = masked max_ce)

// ---------------------------------------------------------------------------
__device__ __forceinline__ float ex2f(float x) {
    float r; asm("ex2.approx.f32 %0, %1;" : "=f"(r) : "f"(x)); return r;
}
__device__ __forceinline__ float lg2f(float x) {
    float r; asm("lg2.approx.f32 %0, %1;" : "=f"(r) : "f"(x)); return r;
}
// softplus(x) = max(x,0) + ln2 * log2(1 + 2^(-|x|*log2e));  2 MUFU + ~4 FMA.
__device__ __forceinline__ float bce(float x, float t) {
    const float LOG2E = 1.4426950408889634f;
    const float LN2   = 0.6931471805599453f;
    const float e  = ex2f(-LOG2E * fabsf(x));
    const float sp = fmaxf(x, 0.0f) + LN2 * lg2f(1.0f + e);
    return sp - t * x;
}
__device__ __forceinline__ float4 bce4(float4 x, float4 t) {
    float4 r;
    r.x = bce(x.x, t.x); r.y = bce(x.y, t.y);
    r.z = bce(x.z, t.z); r.w = bce(x.w, t.w);
    return r;
}

// ---------------------------------------------------------------------------
// Kernel 1: BCE-with-logits + per-anchor max + per-batch bitmasks.
// PDL trigger fires at kernel START: the dependent mask kernel gets scheduled
// while ce streams; its cudaGridDependencySynchronize() still waits for full
// ce completion (memory visibility), but launch latency is hidden.
// ---------------------------------------------------------------------------
__global__ void __launch_bounds__(256) ce_kernel(
    const float* __restrict__ pred,
    const float* __restrict__ tgt,
    const int*   __restrict__ depth,
    float*       __restrict__ out)
{
#if __CUDA_ARCH__ >= 900
    cudaTriggerProgrammaticLaunchCompletion();
#endif
    __shared__ float s_ce[FPB];
    __shared__ float s_m[APB];

    const int tid  = threadIdx.x;
    const int lane = tid & 31;
    const int wid  = tid >> 5;
    const int gbase = blockIdx.x * APB;

    // Prefetch depth EARLY (warp 0, coalesced): hides the dependent LDG
    // under the streaming loads instead of exposing it at the block tail.
    int d_pref = 0;
    if (wid == 0) d_pref = depth[gbase + lane];

    const size_t base4 = (size_t)blockIdx.x * V4PB;
    const float4* __restrict__ p4 = reinterpret_cast<const float4*>(pred) + base4;
    const float4* __restrict__ t4 = reinterpret_cast<const float4*>(tgt)  + base4;
    float4* __restrict__ o4 = reinterpret_cast<float4*>(out) + base4;

    // Front-batched loads: 648 = 256 + 256 + 136.
    const bool has2 = (tid + 512) < V4PB;
    const float4 x0 = __ldcs(&p4[tid]);
    const float4 T0 = __ldcs(&t4[tid]);
    const float4 x1 = __ldcs(&p4[tid + 256]);
    const float4 T1 = __ldcs(&t4[tid + 256]);
    float4 x2, T2;
    if (has2) { x2 = __ldcs(&p4[tid + 512]); T2 = __ldcs(&t4[tid + 512]); }

    const float4 c0 = bce4(x0, T0);
    __stcs(&o4[tid], c0);
    *reinterpret_cast<float4*>(&s_ce[tid * 4]) = c0;

    const float4 c1 = bce4(x1, T1);
    __stcs(&o4[tid + 256], c1);
    *reinterpret_cast<float4*>(&s_ce[(tid + 256) * 4]) = c1;

    if (has2) {
        const float4 c2 = bce4(x2, T2);
        __stcs(&o4[tid + 512], c2);
        *reinterpret_cast<float4*>(&s_ce[(tid + 512) * 4]) = c2;
    }
    __syncthreads();

#pragma unroll
    for (int k = 0; k < APB / 8; k++) {
        const int a = wid + k * 8;
        float m = s_ce[a * C + lane];
        if (lane + 32 < C) m = fmaxf(m, s_ce[a * C + lane + 32]);
        if (lane + 64 < C) m = fmaxf(m, s_ce[a * C + lane + 64]);
#pragma unroll
        for (int off = 16; off; off >>= 1)
            m = fmaxf(m, __shfl_xor_sync(0xffffffffu, m, off));
        if (lane == 0) s_m[a] = m;
    }
    __syncthreads();

    if (wid == 0) {
        const int g = gbase + lane;
        const float meff = (d_pref != 0) ? 0.0f : s_m[lane];
        g_maxce[g] = meff;
        const unsigned posb  = __ballot_sync(0xffffffffu, d_pref > 0);
        const unsigned zerob = __ballot_sync(0xffffffffu, meff == 0.0f);
        if (lane == 0) {
            g_posmask[blockIdx.x]  = posb;
            g_zeromask[blockIdx.x] = zerob;
        }
    }
}

// ---------------------------------------------------------------------------
// Kernel 2: ONE WARP per batch, 32 blocks (latency spread across SMs).
// All 8 LDG.128s issued back-to-back (one L2 round-trip). Warp-autonomous.
// ---------------------------------------------------------------------------
__global__ void __launch_bounds__(32) mask_kernel(
    const int* __restrict__ npr_ptr,
    float*     __restrict__ out)
{
#if __CUDA_ARCH__ >= 900
    cudaGridDependencySynchronize();
#endif
    const int b    = blockIdx.x;
    const int lane = threadIdx.x;
    const unsigned FULL = 0xffffffffu;

    const int ratio = npr_ptr ? *npr_ptr : 3;

    // ---- issue ALL bitmask loads before any use (one L2 round-trip) ----
    const uint4* pp = reinterpret_cast<const uint4*>(g_posmask  + b * WPB) + lane * 4;
    const uint4* zz = reinterpret_cast<const uint4*>(g_zeromask + b * WPB) + lane * 4;
    const uint4 pu0 = pp[0], pu1 = pp[1], pu2 = pp[2], pu3 = pp[3];
    const uint4 zu0 = zz[0], zu1 = zz[1], zu2 = zz[2], zu3 = zz[3];

    uint32_t pw[16] = { pu0.x,pu0.y,pu0.z,pu0.w, pu1.x,pu1.y,pu1.z,pu1.w,
                        pu2.x,pu2.y,pu2.z,pu2.w, pu3.x,pu3.y,pu3.z,pu3.w };
    uint32_t zw[16] = { zu0.x,zu0.y,zu0.z,zu0.w, zu1.x,zu1.y,zu1.z,zu1.w,
                        zu2.x,zu2.y,zu2.z,zu2.w, zu3.x,zu3.y,zu3.z,zu3.w };

    int myz = 0, myp = 0;
#pragma unroll
    for (int j = 0; j < 16; j++) { myz += __popc(zw[j]); myp += __popc(pw[j]); }

    // packed inclusive warp scan: zeros low16, pos high16 (both <= 16384)
    int inc = myz | (myp << 16);
    const int pack = inc;
#pragma unroll
    for (int off = 1; off < 32; off <<= 1) {
        const int n = __shfl_up_sync(FULL, inc, off);
        if (lane >= off) inc += n;
    }
    const int total   = __shfl_sync(FULL, inc, 31);
    const int zbase0  = (inc - pack) & 0xFFFF;   // zeros strictly before my chunk
    const int zeros   = total & 0xFFFF;
    const int num_pos = total >> 16;
    const int cgt     = A - zeros;               // count(v > 0)

    int num_neg = ratio * num_pos;
    if (num_neg > A - 1) num_neg = A - 1;
    if (num_neg < 0)     num_neg = 0;

    if (num_neg == 0 || num_neg > cgt) {
        // ---------------- FAST PATH: vstar == 0 (or no negatives) ----------
        const bool have_neg = (num_neg > 0);
        const int  r_ties   = have_neg ? (num_neg - cgt) : 0;

        int zrun = zbase0;
        const int abase0 = (b * A) + lane * 512;  // my first anchor (global)
#pragma unroll
        for (int j = 0; j < 16; j++) {
            const unsigned zb = zw[j];
            const unsigned pb = pw[j];
            unsigned cand;
            if (!have_neg) {
                cand = ~pb;                       // drop every non-positive
            } else {
                cand = zb & ~pb;                  // potential drops
                if (zrun + __popc(zb) <= r_ties)  // all zeros here still neg
                    cand = 0;
            }
            while (cand) {
                const int bit = __ffs(cand) - 1;
                cand &= cand - 1;
                bool drop = true;
                if (have_neg) {
                    const int zrank = zrun + __popc(zb & ((1u << bit) - 1));
                    drop = (zrank >= r_ties);
                }
                if (drop) {
                    float* row = out + (size_t)(abase0 + j * 32 + bit) * C;
                    for (int c = 0; c < C; c++) row[c] = 0.0f;
                }
            }
            zrun += __popc(zb);
        }
        return;
    }

    // ---------------- SLOW PATH (rare): radix select, 512 values/lane ------
    const uint32_t* vrow = reinterpret_cast<const uint32_t*>(g_maxce) + (size_t)b * A;

    uint32_t vstar = 0;
    int r_ties = 0;
    {
        uint32_t prefix = 0, pmask = 0;
        int rem = num_neg;
        for (int bit = 30; bit >= 0; bit -= 2) {
            unsigned long long pc = 0;
            for (int k = 0; k < 512; k++) {
                const uint32_t v = vrow[lane * 512 + k];
                if ((v & pmask) == prefix) {
                    const unsigned two = (v >> bit) & 3u;
                    pc += (two == 3u) ? (1ull << 42)
                        : (two == 2u) ? (1ull << 21)
                        : (two == 1u) ? 1ull : 0ull;
                }
            }
#pragma unroll
            for (int off = 16; off; off >>= 1) pc += __shfl_xor_sync(FULL, pc, off);

            const int c3 = (int)((pc >> 42) & 0x1FFFFF);
            const int c2 = (int)((pc >> 21) & 0x1FFFFF);
            const int c1 = (int)( pc        & 0x1FFFFF);
            uint32_t sel;
            if      (c3 >= rem)           { sel = 3u; }
            else if (c3 + c2 >= rem)      { sel = 2u; rem -= c3; }
            else if (c3 + c2 + c1 >= rem) { sel = 1u; rem -= c3 + c2; }
            else                          { sel = 0u; rem -= c3 + c2 + c1; }
            prefix |= sel << bit;
            pmask  |= 3u << bit;
        }
        vstar  = prefix;
        r_ties = rem;
    }

    // stable tie rank: warp-exclusive scan of per-lane tie counts
    int myt = 0;
    for (int k = 0; k < 512; k++) myt += (vrow[lane * 512 + k] == vstar);
    int ts = myt;
#pragma unroll
    for (int off = 1; off < 32; off <<= 1) {
        const int n = __shfl_up_sync(FULL, ts, off);
        if (lane >= off) ts += n;
    }
    int tie_idx = ts - myt;   // exclusive base

    for (int k = 0; k < 512; k++) {
        const int a = lane * 512 + k;
        const uint32_t v = vrow[a];
        const bool tie = (v == vstar);
        const bool neg = (v > vstar) || (tie && tie_idx < r_ties);
        if (tie) tie_idx++;
        const bool pos = (pw[k >> 5] >> (a & 31)) & 1u;
        if (!(pos || neg)) {
            float* row = out + ((size_t)b * A + a) * C;
            for (int c = 0; c < C; c++) row[c] = 0.0f;
        }
    }
}

// ---------------------------------------------------------------------------
extern "C" void kernel_launch(void* const* d_in, const int* in_sizes, int n_in,
                              void* d_out, int out_size)
{
    const float* pred  = (const float*)d_in[0];
    const float* tgt   = (const float*)d_in[1];
    const int*   depth = (const int*)d_in[2];
    const int*   npr   = (n_in >= 4) ? (const int*)d_in[3] : nullptr;
    float* out = (float*)d_out;

    ce_kernel<<<(B * A) / APB, 256>>>(pred, tgt, depth, out);

    // PDL launch: 32 blocks x 32 threads (one warp per batch).
    cudaLaunchAttribute attrs[1];
    attrs[0].id = cudaLaunchAttributeProgrammaticStreamSerialization;
    attrs[0].val.programmaticStreamSerializationAllowed = 1;
    cudaLaunchConfig_t cfg = {};
    cfg.gridDim  = dim3(B, 1, 1);
    cfg.blockDim = dim3(32, 1, 1);
    cfg.dynamicSmemBytes = 0;
    cfg.stream = 0;
    cfg.attrs = attrs;
    cfg.numAttrs = 1;
    cudaLaunchKernelEx(&cfg, mask_kernel, npr, out);
}

// round 17
// speedup vs baseline: 1.0135x; 1.0135x over previous
#include <cuda_runtime.h>
#include <cuda_bf16.h>
#include <cstdint>

constexpr int B = 32;
constexpr int A = 16384;
constexpr int C = 81;

constexpr int APB  = 32;            // anchors per ce block
constexpr int FPB  = APB * C;       // 2592 floats
constexpr int V4PB = FPB / 4;       // 648 float4
constexpr int WPB  = A / 32;        // 512 mask words per batch

// Scratch (device globals; no allocations allowed).
__device__ float    g_maxce[B * A];         // slow path only
__device__ unsigned g_posmask[B * WPB];     // bit: depth > 0
__device__ unsigned g_zeromask[B * WPB];    // bit: v == 0  (v = masked max_ce)

// ---------------------------------------------------------------------------
__device__ __forceinline__ float ex2f(float x) {
    float r; asm("ex2.approx.f32 %0, %1;" : "=f"(r) : "f"(x)); return r;
}
__device__ __forceinline__ float lg2f(float x) {
    float r; asm("lg2.approx.f32 %0, %1;" : "=f"(r) : "f"(x)); return r;
}
// softplus(x) = max(x,0) + ln2 * log2(1 + 2^(-|x|*log2e));  2 MUFU + ~4 FMA.
__device__ __forceinline__ float bce(float x, float t) {
    const float LOG2E = 1.4426950408889634f;
    const float LN2   = 0.6931471805599453f;
    const float e  = ex2f(-LOG2E * fabsf(x));
    const float sp = fmaxf(x, 0.0f) + LN2 * lg2f(1.0f + e);
    return sp - t * x;
}
__device__ __forceinline__ float4 bce4(float4 x, float4 t) {
    float4 r;
    r.x = bce(x.x, t.x); r.y = bce(x.y, t.y);
    r.z = bce(x.z, t.z); r.w = bce(x.w, t.w);
    return r;
}

// ---------------------------------------------------------------------------
// Kernel 1: BCE-with-logits + per-anchor max + per-batch bitmasks.
// PDL trigger at END (R15 showed early trigger is a slight pessimization).
// ---------------------------------------------------------------------------
__global__ void __launch_bounds__(256) ce_kernel(
    const float* __restrict__ pred,
    const float* __restrict__ tgt,
    const int*   __restrict__ depth,
    float*       __restrict__ out)
{
    __shared__ float s_ce[FPB];
    __shared__ float s_m[APB];

    const int tid  = threadIdx.x;
    const int lane = tid & 31;
    const int wid  = tid >> 5;
    const int gbase = blockIdx.x * APB;

    // Prefetch depth EARLY (warp 0, coalesced): hides the dependent LDG
    // under the streaming loads instead of exposing it at the block tail.
    int d_pref = 0;
    if (wid == 0) d_pref = depth[gbase + lane];

    const size_t base4 = (size_t)blockIdx.x * V4PB;
    const float4* __restrict__ p4 = reinterpret_cast<const float4*>(pred) + base4;
    const float4* __restrict__ t4 = reinterpret_cast<const float4*>(tgt)  + base4;
    float4* __restrict__ o4 = reinterpret_cast<float4*>(out) + base4;

    // Front-batched loads: 648 = 256 + 256 + 136.
    const bool has2 = (tid + 512) < V4PB;
    const float4 x0 = __ldcs(&p4[tid]);
    const float4 T0 = __ldcs(&t4[tid]);
    const float4 x1 = __ldcs(&p4[tid + 256]);
    const float4 T1 = __ldcs(&t4[tid + 256]);
    float4 x2, T2;
    if (has2) { x2 = __ldcs(&p4[tid + 512]); T2 = __ldcs(&t4[tid + 512]); }

    const float4 c0 = bce4(x0, T0);
    __stcs(&o4[tid], c0);
    *reinterpret_cast<float4*>(&s_ce[tid * 4]) = c0;

    const float4 c1 = bce4(x1, T1);
    __stcs(&o4[tid + 256], c1);
    *reinterpret_cast<float4*>(&s_ce[(tid + 256) * 4]) = c1;

    if (has2) {
        const float4 c2 = bce4(x2, T2);
        __stcs(&o4[tid + 512], c2);
        *reinterpret_cast<float4*>(&s_ce[(tid + 512) * 4]) = c2;
    }
    __syncthreads();

#pragma unroll
    for (int k = 0; k < APB / 8; k++) {
        const int a = wid + k * 8;
        float m = s_ce[a * C + lane];
        if (lane + 32 < C) m = fmaxf(m, s_ce[a * C + lane + 32]);
        if (lane + 64 < C) m = fmaxf(m, s_ce[a * C + lane + 64]);
#pragma unroll
        for (int off = 16; off; off >>= 1)
            m = fmaxf(m, __shfl_xor_sync(0xffffffffu, m, off));
        if (lane == 0) s_m[a] = m;
    }
    __syncthreads();

    if (wid == 0) {
        const int g = gbase + lane;
        const float meff = (d_pref != 0) ? 0.0f : s_m[lane];
        g_maxce[g] = meff;
        const unsigned posb  = __ballot_sync(0xffffffffu, d_pref > 0);
        const unsigned zerob = __ballot_sync(0xffffffffu, meff == 0.0f);
        if (lane == 0) {
            g_posmask[blockIdx.x]  = posb;
            g_zeromask[blockIdx.x] = zerob;
        }
    }

#if __CUDA_ARCH__ >= 900
    cudaTriggerProgrammaticLaunchCompletion();
#endif
}

// ---------------------------------------------------------------------------
// Kernel 2: ONE WARP per batch, 32 blocks (latency spread across SMs).
// npr load hoisted BEFORE the grid sync (input buffer is pre-written by the
// harness, so it's legal and overlaps with the dependency wait).
// ---------------------------------------------------------------------------
__global__ void __launch_bounds__(32) mask_kernel(
    const int* __restrict__ npr_ptr,
    float*     __restrict__ out)
{
    const int ratio = npr_ptr ? *npr_ptr : 3;   // overlaps with the wait below

#if __CUDA_ARCH__ >= 900
    cudaGridDependencySynchronize();
#endif
    const int b    = blockIdx.x;
    const int lane = threadIdx.x;
    const unsigned FULL = 0xffffffffu;

    // ---- issue ALL bitmask loads before any use (one L2 round-trip) ----
    const uint4* pp = reinterpret_cast<const uint4*>(g_posmask  + b * WPB) + lane * 4;
    const uint4* zz = reinterpret_cast<const uint4*>(g_zeromask + b * WPB) + lane * 4;
    const uint4 pu0 = pp[0], pu1 = pp[1], pu2 = pp[2], pu3 = pp[3];
    const uint4 zu0 = zz[0], zu1 = zz[1], zu2 = zz[2], zu3 = zz[3];

    uint32_t pw[16] = { pu0.x,pu0.y,pu0.z,pu0.w, pu1.x,pu1.y,pu1.z,pu1.w,
                        pu2.x,pu2.y,pu2.z,pu2.w, pu3.x,pu3.y,pu3.z,pu3.w };
    uint32_t zw[16] = { zu0.x,zu0.y,zu0.z,zu0.w, zu1.x,zu1.y,zu1.z,zu1.w,
                        zu2.x,zu2.y,zu2.z,zu2.w, zu3.x,zu3.y,zu3.z,zu3.w };

    int myz = 0, myp = 0;
#pragma unroll
    for (int j = 0; j < 16; j++) { myz += __popc(zw[j]); myp += __popc(pw[j]); }

    // packed inclusive warp scan: zeros low16, pos high16 (both <= 16384)
    int inc = myz | (myp << 16);
    const int pack = inc;
#pragma unroll
    for (int off = 1; off < 32; off <<= 1) {
        const int n = __shfl_up_sync(FULL, inc, off);
        if (lane >= off) inc += n;
    }
    const int total   = __shfl_sync(FULL, inc, 31);
    const int zbase0  = (inc - pack) & 0xFFFF;   // zeros strictly before my chunk
    const int zeros   = total & 0xFFFF;
    const int num_pos = total >> 16;
    const int cgt     = A - zeros;               // count(v > 0)

    int num_neg = ratio * num_pos;
    if (num_neg > A - 1) num_neg = A - 1;
    if (num_neg < 0)     num_neg = 0;

    if (num_neg == 0 || num_neg > cgt) {
        // ---------------- FAST PATH: vstar == 0 (or no negatives) ----------
        const bool have_neg = (num_neg > 0);
        const int  r_ties   = have_neg ? (num_neg - cgt) : 0;

        int zrun = zbase0;
        const int abase0 = (b * A) + lane * 512;  // my first anchor (global)
#pragma unroll
        for (int j = 0; j < 16; j++) {
            const unsigned zb = zw[j];
            const unsigned pb = pw[j];
            unsigned cand;
            if (!have_neg) {
                cand = ~pb;                       // drop every non-positive
            } else {
                cand = zb & ~pb;                  // potential drops
                if (zrun + __popc(zb) <= r_ties)  // all zeros here still neg
                    cand = 0;
            }
            while (cand) {
                const int bit = __ffs(cand) - 1;
                cand &= cand - 1;
                bool drop = true;
                if (have_neg) {
                    const int zrank = zrun + __popc(zb & ((1u << bit) - 1));
                    drop = (zrank >= r_ties);
                }
                if (drop) {
                    float* row = out + (size_t)(abase0 + j * 32 + bit) * C;
                    for (int c = 0; c < C; c++) row[c] = 0.0f;
                }
            }
            zrun += __popc(zb);
        }
        return;
    }

    // ---------------- SLOW PATH (rare): radix select, 512 values/lane ------
    const uint32_t* vrow = reinterpret_cast<const uint32_t*>(g_maxce) + (size_t)b * A;

    uint32_t vstar = 0;
    int r_ties = 0;
    {
        uint32_t prefix = 0, pmask = 0;
        int rem = num_neg;
        for (int bit = 30; bit >= 0; bit -= 2) {
            unsigned long long pc = 0;
            for (int k = 0; k < 512; k++) {
                const uint32_t v = vrow[lane * 512 + k];
                if ((v & pmask) == prefix) {
                    const unsigned two = (v >> bit) & 3u;
                    pc += (two == 3u) ? (1ull << 42)
                        : (two == 2u) ? (1ull << 21)
                        : (two == 1u) ? 1ull : 0ull;
                }
            }
#pragma unroll
            for (int off = 16; off; off >>= 1) pc += __shfl_xor_sync(FULL, pc, off);

            const int c3 = (int)((pc >> 42) & 0x1FFFFF);
            const int c2 = (int)((pc >> 21) & 0x1FFFFF);
            const int c1 = (int)( pc        & 0x1FFFFF);
            uint32_t sel;
            if      (c3 >= rem)           { sel = 3u; }
            else if (c3 + c2 >= rem)      { sel = 2u; rem -= c3; }
            else if (c3 + c2 + c1 >= rem) { sel = 1u; rem -= c3 + c2; }
            else                          { sel = 0u; rem -= c3 + c2 + c1; }
            prefix |= sel << bit;
            pmask  |= 3u << bit;
        }
        vstar  = prefix;
        r_ties = rem;
    }

    // stable tie rank: warp-exclusive scan of per-lane tie counts
    int myt = 0;
    for (int k = 0; k < 512; k++) myt += (vrow[lane * 512 + k] == vstar);
    int ts = myt;
#pragma unroll
    for (int off = 1; off < 32; off <<= 1) {
        const int n = __shfl_up_sync(FULL, ts, off);
        if (lane >= off) ts += n;
    }
    int tie_idx = ts - myt;   // exclusive base

    for (int k = 0; k < 512; k++) {
        const int a = lane * 512 + k;
        const uint32_t v = vrow[a];
        const bool tie = (v == vstar);
        const bool neg = (v > vstar) || (tie && tie_idx < r_ties);
        if (tie) tie_idx++;
        const bool pos = (pw[k >> 5] >> (a & 31)) & 1u;
        if (!(pos || neg)) {
            float* row = out + ((size_t)b * A + a) * C;
            for (int c = 0; c < C; c++) row[c] = 0.0f;
        }
    }
}

// ---------------------------------------------------------------------------
extern "C" void kernel_launch(void* const* d_in, const int* in_sizes, int n_in,
                              void* d_out, int out_size)
{
    const float* pred  = (const float*)d_in[0];
    const float* tgt   = (const float*)d_in[1];
    const int*   depth = (const int*)d_in[2];
    const int*   npr   = (n_in >= 4) ? (const int*)d_in[3] : nullptr;
    float* out = (float*)d_out;

    ce_kernel<<<(B * A) / APB, 256>>>(pred, tgt, depth, out);

    // PDL launch: 32 blocks x 32 threads (one warp per batch).
    cudaLaunchAttribute attrs[1];
    attrs[0].id = cudaLaunchAttributeProgrammaticStreamSerialization;
    attrs[0].val.programmaticStreamSerializationAllowed = 1;
    cudaLaunchConfig_t cfg = {};
    cfg.gridDim  = dim3(B, 1, 1);
    cfg.blockDim = dim3(32, 1, 1);
    cfg.dynamicSmemBytes = 0;
    cfg.stream = 0;
    cfg.attrs = attrs;
    cfg.numAttrs = 1;
    cudaLaunchKernelEx(&cfg, mask_kernel, npr, out);
}